// round 12
// baseline (speedup 1.0000x reference)
#include <cuda_runtime.h>

// ---------------------------------------------------------------------------
// InteractingLayer fused kernel v2.1 (fp32, packed f32x2 FMA, 512 thr/CTA)
//   q,k,v,r = x@W^T + b ; S = softmax(q k^T / 8) per head (H=4, D=32)
//   out = relu(S v + r).  One CTA per batch. Weights staged once (all 4),
//   score buffer overlays the dead weight region.
//   v2.1 fix: WT_STRIDE must be EVEN (8-byte ull loads) -> 130.
// ---------------------------------------------------------------------------

#define Fd   40
#define Ed   64
#define OUTd 128

#define XS_STRIDE 68
#define WT_STRIDE 130                  /* EVEN: ull loads need 8B alignment */
#define WT_MAT    (64 * WT_STRIDE)     /* 8320 */
#define QR_STRIDE 132
#define SS_ROW    44
#define SS_HEAD   1764

#define OFF_XS 0                                   /* 40*68   = 2720  */
#define OFF_WT 2720                                /* 4*8320  = 33280 */
#define OFF_QS (OFF_WT + 4 * WT_MAT)               /* 36000           */
#define OFF_KS (OFF_QS + Fd * QR_STRIDE)
#define OFF_VS (OFF_KS + Fd * QR_STRIDE)
#define OFF_RS (OFF_VS + Fd * QR_STRIDE)
#define SMEM_FLOATS (OFF_RS + Fd * QR_STRIDE)      /* 57120 -> 228480 B */
#define SMEM_BYTES  (SMEM_FLOATS * 4)

#define OFF_SS OFF_WT                              /* overlay: 4*1764=7056 */

typedef unsigned long long ull;

__device__ __forceinline__ ull pk2(float a, float b) {
    ull r; asm("mov.b64 %0, {%1,%2};" : "=l"(r) : "f"(a), "f"(b)); return r;
}
__device__ __forceinline__ void unpk2(ull v, float& a, float& b) {
    asm("mov.b64 {%0,%1}, %2;" : "=f"(a), "=f"(b) : "l"(v));
}
__device__ __forceinline__ ull ffma2(ull a, ull b, ull c) {
    ull d; asm("fma.rn.f32x2 %0, %1, %2, %3;" : "=l"(d) : "l"(a), "l"(b), "l"(c));
    return d;
}

__global__ __launch_bounds__(512, 1)
void interacting_layer_kernel(
    const float* __restrict__ x,
    const float* __restrict__ Wq, const float* __restrict__ bq,
    const float* __restrict__ Wk, const float* __restrict__ bk,
    const float* __restrict__ Wv, const float* __restrict__ bv,
    const float* __restrict__ Wr, const float* __restrict__ br,
    float* __restrict__ out)
{
    extern __shared__ float sm[];
    float* xs = sm + OFF_XS;
    float* wt = sm + OFF_WT;
    float* qs = sm + OFF_QS;
    float* ks = sm + OFF_KS;
    float* vs = sm + OFF_VS;
    float* rs = sm + OFF_RS;
    float* ss = sm + OFF_SS;

    const int b = blockIdx.x;
    const int t = threadIdx.x;

    // ================= stage: x tile (float4) + 4 weight matrices ========
    {
        const float4* x4 = (const float4*)(x + (size_t)b * (Fd * Ed));
        for (int i = t; i < Fd * Ed / 4; i += 512) {           // 640 float4
            int f = i >> 4, e4 = i & 15;
            *(float4*)(xs + f * XS_STRIDE + e4 * 4) = x4[i];
        }
        // wt[m][e][col] = W_m[col*64+e]; coalesced GMEM, 2-way STS conflict
        for (int i = t; i < 4 * OUTd * Ed; i += 512) {         // 64 iters
            int m   = i >> 13;
            int r   = i & 8191;
            int col = r >> 6;
            int e   = r & 63;
            const float* Wm = (m == 0) ? Wq : (m == 1) ? Wk : (m == 2) ? Wv : Wr;
            wt[m * WT_MAT + e * WT_STRIDE + col] = Wm[r];
        }
    }
    __syncthreads();

    // ================= projections: all 4 matrices concurrently ==========
    // 128 threads per matrix; thread tile 5 rows x 8 cols (4 col pairs)
    {
        const int mat = t >> 7;
        const int q2  = t & 127;
        const int fT  = q2 >> 4;
        const int cT  = q2 & 15;
        const int f0  = fT * 5;

        const float* myW = wt + mat * WT_MAT + 2 * cT;
        const float* myB = (mat == 0) ? bq : (mat == 1) ? bk : (mat == 2) ? bv : br;
        float*       myO = (mat == 0) ? qs : (mat == 1) ? ks : (mat == 2) ? vs : rs;

        ull acc[5][4];
#pragma unroll
        for (int jp = 0; jp < 4; jp++) {
            float b0 = __ldg(myB + 2 * cT + 32 * jp);
            float b1 = __ldg(myB + 2 * cT + 32 * jp + 1);
            ull bb = pk2(b0, b1);
#pragma unroll
            for (int i = 0; i < 5; i++) acc[i][jp] = bb;
        }

#pragma unroll 4
        for (int e = 0; e < Ed; e++) {
            ull w2[4];
#pragma unroll
            for (int jp = 0; jp < 4; jp++)
                w2[jp] = *(const ull*)(myW + e * WT_STRIDE + 32 * jp);
            ull xx[5];
#pragma unroll
            for (int i = 0; i < 5; i++) {
                float v = xs[(f0 + i) * XS_STRIDE + e];
                xx[i] = pk2(v, v);
            }
#pragma unroll
            for (int i = 0; i < 5; i++)
#pragma unroll
                for (int jp = 0; jp < 4; jp++)
                    acc[i][jp] = ffma2(xx[i], w2[jp], acc[i][jp]);
        }

#pragma unroll
        for (int i = 0; i < 5; i++)
#pragma unroll
            for (int jp = 0; jp < 4; jp++)
                *(ull*)(myO + (f0 + i) * QR_STRIDE + 2 * cT + 32 * jp) = acc[i][jp];
    }
    __syncthreads();   // wt dead from here; ss overlay becomes live

    // ================= scores: S[h][f][g] = (q.k)/8 (packed over d) ======
    if (t < 256) {
        const int h   = t >> 6;
        const int rst = t & 63;
        const int f0s = (rst >> 3) * 5;
        const int g0  = (rst & 7) * 5;

        ull acc2[5][5];
#pragma unroll
        for (int i = 0; i < 5; i++)
#pragma unroll
            for (int j = 0; j < 5; j++) acc2[i][j] = 0ull;

        const float* qb = qs + h * 32;
        const float* kb = ks + h * 32;
#pragma unroll 4
        for (int dp = 0; dp < 16; dp++) {
            ull qv[5], kv[5];
#pragma unroll
            for (int i = 0; i < 5; i++)
                qv[i] = *(const ull*)(qb + (f0s + i) * QR_STRIDE + 2 * dp);
#pragma unroll
            for (int j = 0; j < 5; j++)
                kv[j] = *(const ull*)(kb + (g0 + j) * QR_STRIDE + 2 * dp);
#pragma unroll
            for (int i = 0; i < 5; i++)
#pragma unroll
                for (int j = 0; j < 5; j++)
                    acc2[i][j] = ffma2(qv[i], kv[j], acc2[i][j]);
        }
#pragma unroll
        for (int i = 0; i < 5; i++)
#pragma unroll
            for (int j = 0; j < 5; j++) {
                float a0, a1;
                unpk2(acc2[i][j], a0, a1);
                ss[h * SS_HEAD + (f0s + i) * SS_ROW + g0 + j] = (a0 + a1) * 0.125f;
            }
    }
    __syncthreads();

    // ================= softmax: 2 threads per row, shfl combine ==========
    if (t < 320) {
        const int row  = t >> 1;           // 0..159
        const int half = t & 1;
        const int hh   = row / 40;
        const int ff   = row - hh * 40;
        float* rp = ss + hh * SS_HEAD + ff * SS_ROW + half * 20;

        float v[20];
#pragma unroll
        for (int g = 0; g < 20; g++) v[g] = rp[g];
        float mx = v[0];
#pragma unroll
        for (int g = 1; g < 20; g++) mx = fmaxf(mx, v[g]);
        mx = fmaxf(mx, __shfl_xor_sync(0xffffffffu, mx, 1));
        float sum = 0.f;
#pragma unroll
        for (int g = 0; g < 20; g++) { v[g] = __expf(v[g] - mx); sum += v[g]; }
        sum += __shfl_xor_sync(0xffffffffu, sum, 1);
        float inv = 1.f / sum;
#pragma unroll
        for (int g = 0; g < 20; g++) rp[g] = v[g] * inv;
    }
    __syncthreads();

    // ================= out = relu(S @ v + r) ==============================
    // 128 threads, tile 10 rows x 4 cols; g consumed in pairs (float2 s).
    if (t < 128) {
        const int cg  = t & 31;            // col group: cols 4cg..4cg+3
        const int rg  = t >> 5;            // 0..3 -> rows rg*10..+9
        const int o0  = cg * 4;
        const int f0a = rg * 10;
        const int h2  = cg >> 3;           // head of this col group

        ull acc[10][2];
#pragma unroll
        for (int i = 0; i < 10; i++) {
            acc[i][0] = *(const ull*)(rs + (f0a + i) * QR_STRIDE + o0);
            acc[i][1] = *(const ull*)(rs + (f0a + i) * QR_STRIDE + o0 + 2);
        }

        const float* sb = ss + h2 * SS_HEAD;
#pragma unroll 2
        for (int g = 0; g < Fd; g += 2) {
            ull va0 = *(const ull*)(vs + g * QR_STRIDE + o0);
            ull va1 = *(const ull*)(vs + g * QR_STRIDE + o0 + 2);
            ull vb0 = *(const ull*)(vs + (g + 1) * QR_STRIDE + o0);
            ull vb1 = *(const ull*)(vs + (g + 1) * QR_STRIDE + o0 + 2);
#pragma unroll
            for (int i = 0; i < 10; i++) {
                float2 s2 = *(const float2*)(sb + (f0a + i) * SS_ROW + g);
                ull sa  = pk2(s2.x, s2.x);
                ull sbp = pk2(s2.y, s2.y);
                acc[i][0] = ffma2(sa, va0, acc[i][0]);
                acc[i][1] = ffma2(sa, va1, acc[i][1]);
                acc[i][0] = ffma2(sbp, vb0, acc[i][0]);
                acc[i][1] = ffma2(sbp, vb1, acc[i][1]);
            }
        }

        float* ob = out + (size_t)b * (Fd * OUTd);
#pragma unroll
        for (int i = 0; i < 10; i++) {
            float v0, v1, v2, v3;
            unpk2(acc[i][0], v0, v1);
            unpk2(acc[i][1], v2, v3);
            float4 r4;
            r4.x = fmaxf(v0, 0.f);
            r4.y = fmaxf(v1, 0.f);
            r4.z = fmaxf(v2, 0.f);
            r4.w = fmaxf(v3, 0.f);
            *(float4*)(ob + (f0a + i) * OUTd + o0) = r4;
        }
    }
}

extern "C" void kernel_launch(void* const* d_in, const int* in_sizes, int n_in,
                              void* d_out, int out_size)
{
    const float* x  = (const float*)d_in[0];
    const float* Wq = (const float*)d_in[1];
    const float* bq = (const float*)d_in[2];
    const float* Wk = (const float*)d_in[3];
    const float* bk = (const float*)d_in[4];
    const float* Wv = (const float*)d_in[5];
    const float* bv = (const float*)d_in[6];
    const float* Wr = (const float*)d_in[7];
    const float* br = (const float*)d_in[8];
    float* out = (float*)d_out;

    const int B = in_sizes[0] / (Fd * Ed);

    static int attr_set = 0;
    if (!attr_set) {
        cudaFuncSetAttribute(interacting_layer_kernel,
                             cudaFuncAttributeMaxDynamicSharedMemorySize,
                             SMEM_BYTES);
        attr_set = 1;
    }

    interacting_layer_kernel<<<B, 512, SMEM_BYTES>>>(
        x, Wq, bq, Wk, bk, Wv, bv, Wr, br, out);
}

// round 13
// speedup vs baseline: 1.5625x; 1.5625x over previous
#include <cuda_runtime.h>

// ---------------------------------------------------------------------------
// InteractingLayer fused kernel v2.1 (fp32, packed f32x2 FMA, 512 thr/CTA)
//   q,k,v,r = x@W^T + b ; S = softmax(q k^T / 8) per head (H=4, D=32)
//   out = relu(S v + r).  One CTA per batch. Weights staged once (all 4),
//   score buffer overlays the dead weight region.
//   v2.1 fix: WT_STRIDE must be EVEN (8-byte ull loads) -> 130.
// ---------------------------------------------------------------------------

#define Fd   40
#define Ed   64
#define OUTd 128

#define XS_STRIDE 68
#define WT_STRIDE 130                  /* EVEN: ull loads need 8B alignment */
#define WT_MAT    (64 * WT_STRIDE)     /* 8320 */
#define QR_STRIDE 132
#define SS_ROW    44
#define SS_HEAD   1764

#define OFF_XS 0                                   /* 40*68   = 2720  */
#define OFF_WT 2720                                /* 4*8320  = 33280 */
#define OFF_QS (OFF_WT + 4 * WT_MAT)               /* 36000           */
#define OFF_KS (OFF_QS + Fd * QR_STRIDE)
#define OFF_VS (OFF_KS + Fd * QR_STRIDE)
#define OFF_RS (OFF_VS + Fd * QR_STRIDE)
#define SMEM_FLOATS (OFF_RS + Fd * QR_STRIDE)      /* 57120 -> 228480 B */
#define SMEM_BYTES  (SMEM_FLOATS * 4)

#define OFF_SS OFF_WT                              /* overlay: 4*1764=7056 */

typedef unsigned long long ull;

__device__ __forceinline__ ull pk2(float a, float b) {
    ull r; asm("mov.b64 %0, {%1,%2};" : "=l"(r) : "f"(a), "f"(b)); return r;
}
__device__ __forceinline__ void unpk2(ull v, float& a, float& b) {
    asm("mov.b64 {%0,%1}, %2;" : "=f"(a), "=f"(b) : "l"(v));
}
__device__ __forceinline__ ull ffma2(ull a, ull b, ull c) {
    ull d; asm("fma.rn.f32x2 %0, %1, %2, %3;" : "=l"(d) : "l"(a), "l"(b), "l"(c));
    return d;
}

__global__ __launch_bounds__(512, 1)
void interacting_layer_kernel(
    const float* __restrict__ x,
    const float* __restrict__ Wq, const float* __restrict__ bq,
    const float* __restrict__ Wk, const float* __restrict__ bk,
    const float* __restrict__ Wv, const float* __restrict__ bv,
    const float* __restrict__ Wr, const float* __restrict__ br,
    float* __restrict__ out)
{
    extern __shared__ float sm[];
    float* xs = sm + OFF_XS;
    float* wt = sm + OFF_WT;
    float* qs = sm + OFF_QS;
    float* ks = sm + OFF_KS;
    float* vs = sm + OFF_VS;
    float* rs = sm + OFF_RS;
    float* ss = sm + OFF_SS;

    const int b = blockIdx.x;
    const int t = threadIdx.x;

    // ================= stage: x tile (float4) + 4 weight matrices ========
    {
        const float4* x4 = (const float4*)(x + (size_t)b * (Fd * Ed));
        for (int i = t; i < Fd * Ed / 4; i += 512) {           // 640 float4
            int f = i >> 4, e4 = i & 15;
            *(float4*)(xs + f * XS_STRIDE + e4 * 4) = x4[i];
        }
        // wt[m][e][col] = W_m[col*64+e]; coalesced GMEM, 2-way STS conflict
        for (int i = t; i < 4 * OUTd * Ed; i += 512) {         // 64 iters
            int m   = i >> 13;
            int r   = i & 8191;
            int col = r >> 6;
            int e   = r & 63;
            const float* Wm = (m == 0) ? Wq : (m == 1) ? Wk : (m == 2) ? Wv : Wr;
            wt[m * WT_MAT + e * WT_STRIDE + col] = Wm[r];
        }
    }
    __syncthreads();

    // ================= projections: all 4 matrices concurrently ==========
    // 128 threads per matrix; thread tile 5 rows x 8 cols (4 col pairs)
    {
        const int mat = t >> 7;
        const int q2  = t & 127;
        const int fT  = q2 >> 4;
        const int cT  = q2 & 15;
        const int f0  = fT * 5;

        const float* myW = wt + mat * WT_MAT + 2 * cT;
        const float* myB = (mat == 0) ? bq : (mat == 1) ? bk : (mat == 2) ? bv : br;
        float*       myO = (mat == 0) ? qs : (mat == 1) ? ks : (mat == 2) ? vs : rs;

        ull acc[5][4];
#pragma unroll
        for (int jp = 0; jp < 4; jp++) {
            float b0 = __ldg(myB + 2 * cT + 32 * jp);
            float b1 = __ldg(myB + 2 * cT + 32 * jp + 1);
            ull bb = pk2(b0, b1);
#pragma unroll
            for (int i = 0; i < 5; i++) acc[i][jp] = bb;
        }

#pragma unroll 4
        for (int e = 0; e < Ed; e++) {
            ull w2[4];
#pragma unroll
            for (int jp = 0; jp < 4; jp++)
                w2[jp] = *(const ull*)(myW + e * WT_STRIDE + 32 * jp);
            ull xx[5];
#pragma unroll
            for (int i = 0; i < 5; i++) {
                float v = xs[(f0 + i) * XS_STRIDE + e];
                xx[i] = pk2(v, v);
            }
#pragma unroll
            for (int i = 0; i < 5; i++)
#pragma unroll
                for (int jp = 0; jp < 4; jp++)
                    acc[i][jp] = ffma2(xx[i], w2[jp], acc[i][jp]);
        }

#pragma unroll
        for (int i = 0; i < 5; i++)
#pragma unroll
            for (int jp = 0; jp < 4; jp++)
                *(ull*)(myO + (f0 + i) * QR_STRIDE + 2 * cT + 32 * jp) = acc[i][jp];
    }
    __syncthreads();   // wt dead from here; ss overlay becomes live

    // ================= scores: S[h][f][g] = (q.k)/8 (packed over d) ======
    if (t < 256) {
        const int h   = t >> 6;
        const int rst = t & 63;
        const int f0s = (rst >> 3) * 5;
        const int g0  = (rst & 7) * 5;

        ull acc2[5][5];
#pragma unroll
        for (int i = 0; i < 5; i++)
#pragma unroll
            for (int j = 0; j < 5; j++) acc2[i][j] = 0ull;

        const float* qb = qs + h * 32;
        const float* kb = ks + h * 32;
#pragma unroll 4
        for (int dp = 0; dp < 16; dp++) {
            ull qv[5], kv[5];
#pragma unroll
            for (int i = 0; i < 5; i++)
                qv[i] = *(const ull*)(qb + (f0s + i) * QR_STRIDE + 2 * dp);
#pragma unroll
            for (int j = 0; j < 5; j++)
                kv[j] = *(const ull*)(kb + (g0 + j) * QR_STRIDE + 2 * dp);
#pragma unroll
            for (int i = 0; i < 5; i++)
#pragma unroll
                for (int j = 0; j < 5; j++)
                    acc2[i][j] = ffma2(qv[i], kv[j], acc2[i][j]);
        }
#pragma unroll
        for (int i = 0; i < 5; i++)
#pragma unroll
            for (int j = 0; j < 5; j++) {
                float a0, a1;
                unpk2(acc2[i][j], a0, a1);
                ss[h * SS_HEAD + (f0s + i) * SS_ROW + g0 + j] = (a0 + a1) * 0.125f;
            }
    }
    __syncthreads();

    // ================= softmax: 2 threads per row, shfl combine ==========
    if (t < 320) {
        const int row  = t >> 1;           // 0..159
        const int half = t & 1;
        const int hh   = row / 40;
        const int ff   = row - hh * 40;
        float* rp = ss + hh * SS_HEAD + ff * SS_ROW + half * 20;

        float v[20];
#pragma unroll
        for (int g = 0; g < 20; g++) v[g] = rp[g];
        float mx = v[0];
#pragma unroll
        for (int g = 1; g < 20; g++) mx = fmaxf(mx, v[g]);
        mx = fmaxf(mx, __shfl_xor_sync(0xffffffffu, mx, 1));
        float sum = 0.f;
#pragma unroll
        for (int g = 0; g < 20; g++) { v[g] = __expf(v[g] - mx); sum += v[g]; }
        sum += __shfl_xor_sync(0xffffffffu, sum, 1);
        float inv = 1.f / sum;
#pragma unroll
        for (int g = 0; g < 20; g++) rp[g] = v[g] * inv;
    }
    __syncthreads();

    // ================= out = relu(S @ v + r) ==============================
    // 128 threads, tile 10 rows x 4 cols; g consumed in pairs (float2 s).
    if (t < 128) {
        const int cg  = t & 31;            // col group: cols 4cg..4cg+3
        const int rg  = t >> 5;            // 0..3 -> rows rg*10..+9
        const int o0  = cg * 4;
        const int f0a = rg * 10;
        const int h2  = cg >> 3;           // head of this col group

        ull acc[10][2];
#pragma unroll
        for (int i = 0; i < 10; i++) {
            acc[i][0] = *(const ull*)(rs + (f0a + i) * QR_STRIDE + o0);
            acc[i][1] = *(const ull*)(rs + (f0a + i) * QR_STRIDE + o0 + 2);
        }

        const float* sb = ss + h2 * SS_HEAD;
#pragma unroll 2
        for (int g = 0; g < Fd; g += 2) {
            ull va0 = *(const ull*)(vs + g * QR_STRIDE + o0);
            ull va1 = *(const ull*)(vs + g * QR_STRIDE + o0 + 2);
            ull vb0 = *(const ull*)(vs + (g + 1) * QR_STRIDE + o0);
            ull vb1 = *(const ull*)(vs + (g + 1) * QR_STRIDE + o0 + 2);
#pragma unroll
            for (int i = 0; i < 10; i++) {
                float2 s2 = *(const float2*)(sb + (f0a + i) * SS_ROW + g);
                ull sa  = pk2(s2.x, s2.x);
                ull sbp = pk2(s2.y, s2.y);
                acc[i][0] = ffma2(sa, va0, acc[i][0]);
                acc[i][1] = ffma2(sa, va1, acc[i][1]);
                acc[i][0] = ffma2(sbp, vb0, acc[i][0]);
                acc[i][1] = ffma2(sbp, vb1, acc[i][1]);
            }
        }

        float* ob = out + (size_t)b * (Fd * OUTd);
#pragma unroll
        for (int i = 0; i < 10; i++) {
            float v0, v1, v2, v3;
            unpk2(acc[i][0], v0, v1);
            unpk2(acc[i][1], v2, v3);
            float4 r4;
            r4.x = fmaxf(v0, 0.f);
            r4.y = fmaxf(v1, 0.f);
            r4.z = fmaxf(v2, 0.f);
            r4.w = fmaxf(v3, 0.f);
            *(float4*)(ob + (f0a + i) * OUTd + o0) = r4;
        }
    }
}

extern "C" void kernel_launch(void* const* d_in, const int* in_sizes, int n_in,
                              void* d_out, int out_size)
{
    const float* x  = (const float*)d_in[0];
    const float* Wq = (const float*)d_in[1];
    const float* bq = (const float*)d_in[2];
    const float* Wk = (const float*)d_in[3];
    const float* bk = (const float*)d_in[4];
    const float* Wv = (const float*)d_in[5];
    const float* bv = (const float*)d_in[6];
    const float* Wr = (const float*)d_in[7];
    const float* br = (const float*)d_in[8];
    float* out = (float*)d_out;

    const int B = in_sizes[0] / (Fd * Ed);

    static int attr_set = 0;
    if (!attr_set) {
        cudaFuncSetAttribute(interacting_layer_kernel,
                             cudaFuncAttributeMaxDynamicSharedMemorySize,
                             SMEM_BYTES);
        attr_set = 1;
    }

    interacting_layer_kernel<<<B, 512, SMEM_BYTES>>>(
        x, Wq, bq, Wk, bk, Wv, bv, Wr, br, out);
}

// round 14
// speedup vs baseline: 1.9754x; 1.2643x over previous
#include <cuda_runtime.h>

// ---------------------------------------------------------------------------
// InteractingLayer fused kernel v3
//   - prep kernel pre-transposes all 4 weight matrices into g_wt (gmem)
//   - main kernel: straight float4 staging, dup-pair x, packed f32x2 FMA
//   - q/k/v/r overlay the xd/wt staging region (acc carried over a barrier)
//   - softmax writes duplicated (s,s) pairs so AV needs no packing movs
// ---------------------------------------------------------------------------

#define Fd   40
#define Ed   64
#define OUTd 128

#define XD_STRIDE 136                  /* dup x row: 128 floats + pad */
#define WT_STRIDE 130
#define WT_MAT    (64 * WT_STRIDE)     /* 8320 floats per matrix */
#define QR_STRIDE 132
#define SS_ROW    44
#define SS_HEAD   1764
#define SSD_ROW   88
#define SSD_HEAD  3528

/* phase-1 (staging/projection) layout */
#define OFF_XD 0                       /* 40*136 = 5440 */
#define OFF_WT 5440                    /* 4*8320 = 33280 -> end 38720 */
/* phase-2+ layout (overlays phase-1; acc in regs across the barrier) */
#define OFF_QS 0
#define OFF_KS (OFF_QS + Fd * QR_STRIDE)     /* 5280  */
#define OFF_VS (OFF_KS + Fd * QR_STRIDE)     /* 10560 */
#define OFF_RS (OFF_VS + Fd * QR_STRIDE)     /* 15840 */
#define OFF_SS (OFF_RS + Fd * QR_STRIDE)     /* 21120, 4*1764 = 7056 */
#define OFF_SSD (OFF_SS + 4 * SS_HEAD)       /* 28176, 4*3528 = 14112 */
#define SMEM_FLOATS (OFF_SSD + 4 * SSD_HEAD) /* 42288 -> 169152 B */
#define SMEM_BYTES  (SMEM_FLOATS * 4)

typedef unsigned long long ull;

__device__ float g_wt[4 * WT_MAT];     /* transposed weights, 133 KB */

__device__ __forceinline__ ull pk2(float a, float b) {
    ull r; asm("mov.b64 %0, {%1,%2};" : "=l"(r) : "f"(a), "f"(b)); return r;
}
__device__ __forceinline__ void unpk2(ull v, float& a, float& b) {
    asm("mov.b64 {%0,%1}, %2;" : "=f"(a), "=f"(b) : "l"(v));
}
__device__ __forceinline__ ull ffma2(ull a, ull b, ull c) {
    ull d; asm("fma.rn.f32x2 %0, %1, %2, %3;" : "=l"(d) : "l"(a), "l"(b), "l"(c));
    return d;
}

// ---------------- prep: wt[m][e][col] = W_m[col*64 + e] --------------------
__global__ void prep_wt_kernel(const float* __restrict__ Wq,
                               const float* __restrict__ Wk,
                               const float* __restrict__ Wv,
                               const float* __restrict__ Wr)
{
    int i = blockIdx.x * blockDim.x + threadIdx.x;   // 0..32767
    int m   = i >> 13;
    int r   = i & 8191;
    int col = r >> 6;
    int e   = r & 63;
    const float* Wm = (m == 0) ? Wq : (m == 1) ? Wk : (m == 2) ? Wv : Wr;
    g_wt[m * WT_MAT + e * WT_STRIDE + col] = Wm[r];
}

// ---------------- main fused kernel ----------------------------------------
__global__ __launch_bounds__(512, 1)
void interacting_layer_kernel(
    const float* __restrict__ x,
    const float* __restrict__ bq, const float* __restrict__ bk,
    const float* __restrict__ bv, const float* __restrict__ br,
    float* __restrict__ out)
{
    extern __shared__ float sm[];
    float* xd  = sm + OFF_XD;
    float* wt  = sm + OFF_WT;
    float* qs  = sm + OFF_QS;
    float* ks  = sm + OFF_KS;
    float* vs  = sm + OFF_VS;
    float* rs  = sm + OFF_RS;
    float* ss  = sm + OFF_SS;
    float* ssd = sm + OFF_SSD;

    const int b = blockIdx.x;
    const int t = threadIdx.x;

    // ===== stage: dup-pair x + straight float4 copy of transposed W ======
    {
        const float2* x2 = (const float2*)(x + (size_t)b * (Fd * Ed));
#pragma unroll
        for (int k = 0; k < 3; k++) {
            int i = t + k * 512;
            if (i < Fd * Ed / 2) {                 // 1280 float2
                int f  = i >> 5;
                int ep = i & 31;
                float2 v = x2[i];
                float4 d;
                d.x = v.x; d.y = v.x; d.z = v.y; d.w = v.y;
                *(float4*)(xd + f * XD_STRIDE + ep * 4) = d;
            }
        }
        const float4* gw4 = (const float4*)g_wt;
        float4* wt4 = (float4*)wt;
        for (int i = t; i < 4 * WT_MAT / 4; i += 512)   // 8320 float4
            wt4[i] = gw4[i];
    }
    __syncthreads();

    // ===== projections: all 4 matrices concurrently =======================
    // 128 threads/matrix; thread tile 5 rows x 8 cols (4 packed col pairs)
    {
        const int mat = t >> 7;
        const int q2  = t & 127;
        const int fT  = q2 >> 4;
        const int cT  = q2 & 15;
        const int f0  = fT * 5;

        const float* myW = wt + mat * WT_MAT + 2 * cT;
        const float* myB = (mat == 0) ? bq : (mat == 1) ? bk : (mat == 2) ? bv : br;
        float*       myO = (mat == 0) ? qs : (mat == 1) ? ks : (mat == 2) ? vs : rs;

        ull acc[5][4];
#pragma unroll
        for (int jp = 0; jp < 4; jp++) {
            float b0 = __ldg(myB + 2 * cT + 32 * jp);
            float b1 = __ldg(myB + 2 * cT + 32 * jp + 1);
            ull bb = pk2(b0, b1);
#pragma unroll
            for (int i = 0; i < 5; i++) acc[i][jp] = bb;
        }

#pragma unroll 4
        for (int e = 0; e < Ed; e++) {
            ull w2[4];
#pragma unroll
            for (int jp = 0; jp < 4; jp++)
                w2[jp] = *(const ull*)(myW + e * WT_STRIDE + 32 * jp);
            ull xx[5];
#pragma unroll
            for (int i = 0; i < 5; i++)
                xx[i] = *(const ull*)(xd + (f0 + i) * XD_STRIDE + 2 * e);
#pragma unroll
            for (int i = 0; i < 5; i++)
#pragma unroll
                for (int jp = 0; jp < 4; jp++)
                    acc[i][jp] = ffma2(xx[i], w2[jp], acc[i][jp]);
        }

        __syncthreads();   // xd/wt dead; safe to overlay with q/k/v/r

#pragma unroll
        for (int i = 0; i < 5; i++)
#pragma unroll
            for (int jp = 0; jp < 4; jp++)
                *(ull*)(myO + (f0 + i) * QR_STRIDE + 2 * cT + 32 * jp) = acc[i][jp];
    }
    __syncthreads();

    // ===== scores: S[h][f][g] = (q.k)/8 (packed over d) ===================
    if (t < 256) {
        const int h   = t >> 6;
        const int rst = t & 63;
        const int f0s = (rst >> 3) * 5;
        const int g0  = (rst & 7) * 5;

        ull acc2[5][5];
#pragma unroll
        for (int i = 0; i < 5; i++)
#pragma unroll
            for (int j = 0; j < 5; j++) acc2[i][j] = 0ull;

        const float* qb = qs + h * 32;
        const float* kb = ks + h * 32;
#pragma unroll 4
        for (int dp = 0; dp < 16; dp++) {
            ull qv[5], kv[5];
#pragma unroll
            for (int i = 0; i < 5; i++)
                qv[i] = *(const ull*)(qb + (f0s + i) * QR_STRIDE + 2 * dp);
#pragma unroll
            for (int j = 0; j < 5; j++)
                kv[j] = *(const ull*)(kb + (g0 + j) * QR_STRIDE + 2 * dp);
#pragma unroll
            for (int i = 0; i < 5; i++)
#pragma unroll
                for (int j = 0; j < 5; j++)
                    acc2[i][j] = ffma2(qv[i], kv[j], acc2[i][j]);
        }
#pragma unroll
        for (int i = 0; i < 5; i++)
#pragma unroll
            for (int j = 0; j < 5; j++) {
                float a0, a1;
                unpk2(acc2[i][j], a0, a1);
                ss[h * SS_HEAD + (f0s + i) * SS_ROW + g0 + j] = (a0 + a1) * 0.125f;
            }
    }
    __syncthreads();

    // ===== softmax: 2 threads/row, shfl combine; writes DUPLICATED ========
    if (t < 320) {
        const int row  = t >> 1;
        const int half = t & 1;
        const int hh   = row / 40;
        const int ff   = row - hh * 40;
        const float* rp = ss  + hh * SS_HEAD  + ff * SS_ROW  + half * 20;
        float*       wp = ssd + hh * SSD_HEAD + ff * SSD_ROW + half * 40;

        float v[20];
#pragma unroll
        for (int g = 0; g < 20; g++) v[g] = rp[g];
        float mx = v[0];
#pragma unroll
        for (int g = 1; g < 20; g++) mx = fmaxf(mx, v[g]);
        mx = fmaxf(mx, __shfl_xor_sync(0xffffffffu, mx, 1));
        float sum = 0.f;
#pragma unroll
        for (int g = 0; g < 20; g++) { v[g] = __expf(v[g] - mx); sum += v[g]; }
        sum += __shfl_xor_sync(0xffffffffu, sum, 1);
        float inv = 1.f / sum;
#pragma unroll
        for (int g = 0; g < 20; g++) {
            float s = v[g] * inv;
            float2 d; d.x = s; d.y = s;
            *(float2*)(wp + 2 * g) = d;
        }
    }
    __syncthreads();

    // ===== out = relu(S @ v + r): 128 thr, tile 10 rows x 4 cols ==========
    if (t < 128) {
        const int cg  = t & 31;
        const int rg  = t >> 5;
        const int o0  = cg * 4;
        const int f0a = rg * 10;
        const int h2  = cg >> 3;

        ull acc[10][2];
#pragma unroll
        for (int i = 0; i < 10; i++) {
            ulonglong2 r2 = *(const ulonglong2*)(rs + (f0a + i) * QR_STRIDE + o0);
            acc[i][0] = r2.x;
            acc[i][1] = r2.y;
        }

        const float* sb = ssd + h2 * SSD_HEAD;
#pragma unroll 2
        for (int g = 0; g < Fd; g += 2) {
            ulonglong2 va = *(const ulonglong2*)(vs + g * QR_STRIDE + o0);
            ulonglong2 vb = *(const ulonglong2*)(vs + (g + 1) * QR_STRIDE + o0);
            const float* sp = sb + 2 * g;
#pragma unroll
            for (int i = 0; i < 10; i++) {
                ulonglong2 s4 = *(const ulonglong2*)(sp + (f0a + i) * SSD_ROW);
                acc[i][0] = ffma2(s4.x, va.x, acc[i][0]);
                acc[i][1] = ffma2(s4.x, va.y, acc[i][1]);
                acc[i][0] = ffma2(s4.y, vb.x, acc[i][0]);
                acc[i][1] = ffma2(s4.y, vb.y, acc[i][1]);
            }
        }

        float* ob = out + (size_t)b * (Fd * OUTd);
#pragma unroll
        for (int i = 0; i < 10; i++) {
            float v0, v1, v2, v3;
            unpk2(acc[i][0], v0, v1);
            unpk2(acc[i][1], v2, v3);
            float4 r4;
            r4.x = fmaxf(v0, 0.f);
            r4.y = fmaxf(v1, 0.f);
            r4.z = fmaxf(v2, 0.f);
            r4.w = fmaxf(v3, 0.f);
            *(float4*)(ob + (f0a + i) * OUTd + o0) = r4;
        }
    }
}

extern "C" void kernel_launch(void* const* d_in, const int* in_sizes, int n_in,
                              void* d_out, int out_size)
{
    const float* x  = (const float*)d_in[0];
    const float* Wq = (const float*)d_in[1];
    const float* bq = (const float*)d_in[2];
    const float* Wk = (const float*)d_in[3];
    const float* bk = (const float*)d_in[4];
    const float* Wv = (const float*)d_in[5];
    const float* bv = (const float*)d_in[6];
    const float* Wr = (const float*)d_in[7];
    const float* br = (const float*)d_in[8];
    float* out = (float*)d_out;

    const int B = in_sizes[0] / (Fd * Ed);

    static int attr_set = 0;
    if (!attr_set) {
        cudaFuncSetAttribute(interacting_layer_kernel,
                             cudaFuncAttributeMaxDynamicSharedMemorySize,
                             SMEM_BYTES);
        attr_set = 1;
    }

    prep_wt_kernel<<<64, 512>>>(Wq, Wk, Wv, Wr);
    interacting_layer_kernel<<<B, 512, SMEM_BYTES>>>(
        x, bq, bk, bv, br, out);
}

// round 15
// speedup vs baseline: 2.4516x; 1.2411x over previous
#include <cuda_runtime.h>

// ---------------------------------------------------------------------------
// InteractingLayer fused kernel v4: 256 thr/CTA, 2 CTAs/SM (112.7KB smem each)
//   - prep kernel pre-transposes W into g_wt, chunk-contiguous:
//       g_wt[chunk][m][e_local][col], chunk = e/32
//   - main kernel: weights staged in 2 chunks (straight float4 copy),
//     dup-pair x, packed f32x2 FMA everywhere, q/k/v/r+ss overlay staging.
// ---------------------------------------------------------------------------

#define Fd   40
#define Ed   64
#define OUTd 128

#define XD_STRIDE 136
#define WT_STRIDE 130
#define CHUNK_E   32
#define WT_MAT_C  (CHUNK_E * WT_STRIDE)        /* 4160 floats per mat/chunk */
#define WT_CHUNK  (4 * WT_MAT_C)               /* 16640 floats per chunk    */
#define QR_STRIDE 132
#define SS_ROW    44
#define SS_HEAD   1764

/* phase-1 (staging/projection) layout */
#define OFF_XD  0                              /* 40*136 = 5440       */
#define OFF_WTS 5440                           /* 16640 -> end 22080  */
/* phase-2 layout (overlays phase-1; acc carried in regs) */
#define OFF_QS  0
#define OFF_KS  (OFF_QS + Fd * QR_STRIDE)      /* 5280  */
#define OFF_VS  (OFF_KS + Fd * QR_STRIDE)      /* 10560 */
#define OFF_RS  (OFF_VS + Fd * QR_STRIDE)      /* 15840 */
#define OFF_SS  (OFF_RS + Fd * QR_STRIDE)      /* 21120, 4*1764=7056  */
#define SMEM_FLOATS (OFF_SS + 4 * SS_HEAD)     /* 28176 -> 112704 B   */
#define SMEM_BYTES  (SMEM_FLOATS * 4)

typedef unsigned long long ull;

__device__ float g_wt[2 * WT_CHUNK];           /* 133 KB, chunk-contiguous */

__device__ __forceinline__ ull pk2(float a, float b) {
    ull r; asm("mov.b64 %0, {%1,%2};" : "=l"(r) : "f"(a), "f"(b)); return r;
}
__device__ __forceinline__ void unpk2(ull v, float& a, float& b) {
    asm("mov.b64 {%0,%1}, %2;" : "=f"(a), "=f"(b) : "l"(v));
}
__device__ __forceinline__ ull ffma2(ull a, ull b, ull c) {
    ull d; asm("fma.rn.f32x2 %0, %1, %2, %3;" : "=l"(d) : "l"(a), "l"(b), "l"(c));
    return d;
}

// ---- prep: g_wt[chunk][m][e&31][col] = W_m[col*64 + e] --------------------
__global__ void prep_wt_kernel(const float* __restrict__ Wq,
                               const float* __restrict__ Wk,
                               const float* __restrict__ Wv,
                               const float* __restrict__ Wr)
{
    int i = blockIdx.x * blockDim.x + threadIdx.x;   // 0..32767
    int m   = i >> 13;
    int r   = i & 8191;
    int col = r >> 6;
    int e   = r & 63;
    int ch  = e >> 5;
    int el  = e & 31;
    const float* Wm = (m == 0) ? Wq : (m == 1) ? Wk : (m == 2) ? Wv : Wr;
    g_wt[ch * WT_CHUNK + m * WT_MAT_C + el * WT_STRIDE + col] = Wm[r];
}

// ---- main fused kernel ------------------------------------------------------
__global__ __launch_bounds__(256, 2)
void interacting_layer_kernel(
    const float* __restrict__ x,
    const float* __restrict__ bq, const float* __restrict__ bk,
    const float* __restrict__ bv, const float* __restrict__ br,
    float* __restrict__ out)
{
    extern __shared__ float sm[];
    float* xd  = sm + OFF_XD;
    float* wts = sm + OFF_WTS;
    float* qs  = sm + OFF_QS;
    float* ks  = sm + OFF_KS;
    float* vs  = sm + OFF_VS;
    float* rs  = sm + OFF_RS;
    float* ss  = sm + OFF_SS;

    const int b = blockIdx.x;
    const int t = threadIdx.x;

    // ===== projection setup: 64 threads per matrix ========================
    // thread tile: 5 rows x 8 interleaved col-pairs {2cT+16j, 2cT+16j+1}
    const int mat = t >> 6;
    const int q2  = t & 63;
    const int f0  = (q2 >> 3) * 5;
    const int cT  = q2 & 7;

    const float* myB = (mat == 0) ? bq : (mat == 1) ? bk : (mat == 2) ? bv : br;
    float*       myO = (mat == 0) ? qs : (mat == 1) ? ks : (mat == 2) ? vs : rs;

    ull acc[5][8];
#pragma unroll
    for (int j = 0; j < 8; j++) {
        float b0 = __ldg(myB + 2 * cT + 16 * j);
        float b1 = __ldg(myB + 2 * cT + 16 * j + 1);
        ull bb = pk2(b0, b1);
#pragma unroll
        for (int i = 0; i < 5; i++) acc[i][j] = bb;
    }

    // ===== two weight chunks: stage -> sync -> accumulate -> sync =========
#pragma unroll 1
    for (int c = 0; c < 2; c++) {
        {
            const float4* gw4 = (const float4*)g_wt + c * (WT_CHUNK / 4);
            float4* wt4 = (float4*)wts;
            for (int i = t; i < WT_CHUNK / 4; i += 256)   // 4160 float4
                wt4[i] = gw4[i];
            if (c == 0) {
                const float2* x2 = (const float2*)(x + (size_t)b * (Fd * Ed));
#pragma unroll
                for (int k = 0; k < 5; k++) {
                    int i = t + k * 256;                   // 1280 float2
                    int f  = i >> 5;
                    int ep = i & 31;
                    float2 v = x2[i];
                    float4 d;
                    d.x = v.x; d.y = v.x; d.z = v.y; d.w = v.y;
                    *(float4*)(xd + f * XD_STRIDE + ep * 4) = d;
                }
            }
        }
        __syncthreads();

        const float* myW = wts + mat * WT_MAT_C + 2 * cT;
        const float* myX = xd + f0 * XD_STRIDE + 2 * c * CHUNK_E;
#pragma unroll 4
        for (int el = 0; el < CHUNK_E; el++) {
            ull w2[8];
#pragma unroll
            for (int j = 0; j < 8; j++)
                w2[j] = *(const ull*)(myW + el * WT_STRIDE + 16 * j);
            ull xx[5];
#pragma unroll
            for (int i = 0; i < 5; i++)
                xx[i] = *(const ull*)(myX + i * XD_STRIDE + 2 * el);
#pragma unroll
            for (int i = 0; i < 5; i++)
#pragma unroll
                for (int j = 0; j < 8; j++)
                    acc[i][j] = ffma2(xx[i], w2[j], acc[i][j]);
        }
        __syncthreads();   // after c=1 this also frees xd/wts for overlay
    }

    // ===== write q/k/v/r (overlays staging region) ========================
#pragma unroll
    for (int i = 0; i < 5; i++)
#pragma unroll
        for (int j = 0; j < 8; j++)
            *(ull*)(myO + (f0 + i) * QR_STRIDE + 2 * cT + 16 * j) = acc[i][j];
    __syncthreads();

    // ===== scores: S[h][f][g] = (q.k)/8 (packed over d) ===================
    {
        const int h   = t >> 6;
        const int rst = t & 63;
        const int f0s = (rst >> 3) * 5;
        const int g0  = (rst & 7) * 5;

        ull acc2[5][5];
#pragma unroll
        for (int i = 0; i < 5; i++)
#pragma unroll
            for (int j = 0; j < 5; j++) acc2[i][j] = 0ull;

        const float* qb = qs + h * 32;
        const float* kb = ks + h * 32;
#pragma unroll 4
        for (int dp = 0; dp < 16; dp++) {
            ull qv[5], kv[5];
#pragma unroll
            for (int i = 0; i < 5; i++)
                qv[i] = *(const ull*)(qb + (f0s + i) * QR_STRIDE + 2 * dp);
#pragma unroll
            for (int j = 0; j < 5; j++)
                kv[j] = *(const ull*)(kb + (g0 + j) * QR_STRIDE + 2 * dp);
#pragma unroll
            for (int i = 0; i < 5; i++)
#pragma unroll
                for (int j = 0; j < 5; j++)
                    acc2[i][j] = ffma2(qv[i], kv[j], acc2[i][j]);
        }
#pragma unroll
        for (int i = 0; i < 5; i++)
#pragma unroll
            for (int j = 0; j < 5; j++) {
                float a0, a1;
                unpk2(acc2[i][j], a0, a1);
                ss[h * SS_HEAD + (f0s + i) * SS_ROW + g0 + j] = (a0 + a1) * 0.125f;
            }
    }
    __syncthreads();

    // ===== softmax: 1 thread per row (160 rows), float4 row I/O ===========
    if (t < 160) {
        const int hh = t / Fd;
        const int ff = t - hh * Fd;
        float* rp = ss + hh * SS_HEAD + ff * SS_ROW;

        float4 v4[10];
#pragma unroll
        for (int g = 0; g < 10; g++) v4[g] = *(const float4*)(rp + 4 * g);
        float* v = (float*)v4;
        float mx = v[0];
#pragma unroll
        for (int g = 1; g < Fd; g++) mx = fmaxf(mx, v[g]);
        float sum = 0.f;
#pragma unroll
        for (int g = 0; g < Fd; g++) { v[g] = __expf(v[g] - mx); sum += v[g]; }
        float inv = 1.f / sum;
#pragma unroll
        for (int g = 0; g < Fd; g++) v[g] *= inv;
#pragma unroll
        for (int g = 0; g < 10; g++) *(float4*)(rp + 4 * g) = v4[g];
    }
    __syncthreads();

    // ===== out = relu(S @ v + r): tile 5 rows x 4 cols ====================
    // rg = t&7 (rows), cg = t>>3 (col chunk) -> warp shares v/s via broadcast
    {
        const int rg  = t & 7;
        const int cg  = t >> 3;
        const int o0  = cg * 4;
        const int f0a = rg * 5;
        const int h2  = cg >> 3;

        ull av[5][2];
#pragma unroll
        for (int i = 0; i < 5; i++) {
            ulonglong2 r2 = *(const ulonglong2*)(rs + (f0a + i) * QR_STRIDE + o0);
            av[i][0] = r2.x;
            av[i][1] = r2.y;
        }

        const float* sb = ss + h2 * SS_HEAD;
#pragma unroll 2
        for (int g = 0; g < Fd; g += 2) {
            ulonglong2 va = *(const ulonglong2*)(vs + g * QR_STRIDE + o0);
            ulonglong2 vb = *(const ulonglong2*)(vs + (g + 1) * QR_STRIDE + o0);
#pragma unroll
            for (int i = 0; i < 5; i++) {
                float2 s2 = *(const float2*)(sb + (f0a + i) * SS_ROW + g);
                ull sa  = pk2(s2.x, s2.x);
                ull sbp = pk2(s2.y, s2.y);
                av[i][0] = ffma2(sa, va.x, av[i][0]);
                av[i][1] = ffma2(sa, va.y, av[i][1]);
                av[i][0] = ffma2(sbp, vb.x, av[i][0]);
                av[i][1] = ffma2(sbp, vb.y, av[i][1]);
            }
        }

        float* ob = out + (size_t)b * (Fd * OUTd);
#pragma unroll
        for (int i = 0; i < 5; i++) {
            float v0, v1, v2, v3;
            unpk2(av[i][0], v0, v1);
            unpk2(av[i][1], v2, v3);
            float4 r4;
            r4.x = fmaxf(v0, 0.f);
            r4.y = fmaxf(v1, 0.f);
            r4.z = fmaxf(v2, 0.f);
            r4.w = fmaxf(v3, 0.f);
            *(float4*)(ob + (f0a + i) * OUTd + o0) = r4;
        }
    }
}

extern "C" void kernel_launch(void* const* d_in, const int* in_sizes, int n_in,
                              void* d_out, int out_size)
{
    const float* x  = (const float*)d_in[0];
    const float* Wq = (const float*)d_in[1];
    const float* bq = (const float*)d_in[2];
    const float* Wk = (const float*)d_in[3];
    const float* bk = (const float*)d_in[4];
    const float* Wv = (const float*)d_in[5];
    const float* bv = (const float*)d_in[6];
    const float* Wr = (const float*)d_in[7];
    const float* br = (const float*)d_in[8];
    float* out = (float*)d_out;

    const int B = in_sizes[0] / (Fd * Ed);

    static int attr_set = 0;
    if (!attr_set) {
        cudaFuncSetAttribute(interacting_layer_kernel,
                             cudaFuncAttributeMaxDynamicSharedMemorySize,
                             SMEM_BYTES);
        attr_set = 1;
    }

    prep_wt_kernel<<<64, 512>>>(Wq, Wk, Wv, Wr);
    interacting_layer_kernel<<<B, 256, SMEM_BYTES>>>(
        x, bq, bk, bv, br, out);
}